// round 8
// baseline (speedup 1.0000x reference)
#include <cuda_runtime.h>
#include <cuda_bf16.h>
#include <math.h>

// Problem constants (fixed shapes from reference):
//   x, mix: [8, 192, 64, 64] fp32 ; W: [191, 192] ; b: [191]
//   outputs: ybar [8,192,64,64] then mix_out [8,192,64,64], contiguous in d_out.
//   Total out elements = 2 * 6291456 = 12582912 = out_size.
#define CCH   192
#define TT    16          // channel tile
#define NTIL  12          // 192 / 16
#define BLOCK 128         // threads per block = pixels per block
#define NPIX  32768       // 8 * 64 * 64
#define ACC_STRIDE 193    // 193 mod 32 == 1 -> conflict-free per-thread rows
#define NCHW  6291456     // 8*192*64*64  (R7 fix: was erroneously 2x this)

__global__ void __launch_bounds__(BLOCK, 2)
chan_deps_kernel(const float* __restrict__ x,
                 const float* __restrict__ mix,
                 const float* __restrict__ W,
                 const float* __restrict__ b,
                 float* __restrict__ ybar_out,
                 float* __restrict__ mix_out)
{
    extern __shared__ float smem[];
    float* acc_s = smem;                         // [BLOCK][ACC_STRIDE]
    float* Wc    = smem + BLOCK * ACC_STRIDE;    // staged W slab, up to 191*16 floats

    const int tid = threadIdx.x;
    const int p   = blockIdx.x * BLOCK + tid;    // pixel id, grid is exact
    const int n   = p >> 12;                     // p / 4096   (H*W = 4096)
    const int hw  = p & 4095;

    float* accp = acc_s + tid * ACC_STRIDE;

    // zero per-pixel accumulators (cross-tile partial sums, channels 0..191)
    #pragma unroll 8
    for (int c = 0; c < CCH; c++) accp[c] = 0.0f;

    for (int t = 0; t < NTIL; t++) {
        const int cbase = t * TT;
        const int cend  = cbase + TT;

        // ---- stage W slab: Wc[r][j] = W[cbase + r][cbase + j],
        //      r = 0 .. (190 - cbase), j = 0..15.  Covers the in-tile
        //      triangular block (rows 0..14) and all cross-tile rows.
        const int nrows = 191 - cbase;
        __syncthreads();                         // prior tile finished reading Wc
        for (int idx = tid; idx < nrows * TT; idx += BLOCK) {
            const int r = idx >> 4;
            const int j = idx & 15;
            Wc[idx] = __ldg(&W[(cbase + r) * CCH + cbase + j]);
        }
        __syncthreads();

        // ---- load this tile's x / mix for my pixel (coalesced across threads)
        float xv[TT], mv[TT];
        #pragma unroll
        for (int i = 0; i < TT; i++) {
            const int gi = ((n * CCH + (cbase + i)) << 12) + hw;
            xv[i] = __ldg(&x[gi]);
            mv[i] = __ldg(&mix[gi]);
        }

        // ---- sequential in-tile recurrence (ybar + within-tile updates)
        float part[TT];
        #pragma unroll
        for (int i = 0; i < TT; i++) part[i] = 0.0f;

        float yr[TT];
        #pragma unroll
        for (int i = 0; i < TT; i++) {
            const int c = cbase + i;
            float m;
            if (c == 0) {
                m = mv[0];                               // channel 0: no conv, no bias
            } else {
                m = accp[c] + __ldg(&b[c - 1]) + mv[i] + part[i];
            }
            const float y = rintf(xv[i] - m) + m;        // half-to-even like jnp.round
            yr[i] = y;
            const int gi = ((n * CCH + c) << 12) + hw;
            ybar_out[gi] = y;
            mix_out[gi]  = m;
            // push y's contribution to later channels inside this tile
            #pragma unroll
            for (int i2 = i + 1; i2 < TT; i2++) {
                // W[(cbase+i2)-1][c] = Wc[i2-1][i]
                part[i2] = fmaf(Wc[(i2 - 1) * TT + i], y, part[i2]);
            }
        }

        // ---- cross-tile rank-16 update: acc[c2] += W[c2-1, cbase:cbase+16] . yr
        //      (192 - cend) is a multiple of 16 -> unroll by 4 c2's for ILP.
        for (int c2 = cend; c2 < CCH; c2 += 4) {
            const float* w0 = Wc + (c2 - 1 - cbase) * TT;
            const float* w1 = w0 + TT;
            const float* w2 = w1 + TT;
            const float* w3 = w2 + TT;
            float s0 = 0.0f, s1 = 0.0f, s2 = 0.0f, s3 = 0.0f;
            #pragma unroll
            for (int j = 0; j < TT; j++) {
                const float yv = yr[j];
                s0 = fmaf(w0[j], yv, s0);
                s1 = fmaf(w1[j], yv, s1);
                s2 = fmaf(w2[j], yv, s2);
                s3 = fmaf(w3[j], yv, s3);
            }
            accp[c2 + 0] += s0;
            accp[c2 + 1] += s1;
            accp[c2 + 2] += s2;
            accp[c2 + 3] += s3;
        }
    }
}

extern "C" void kernel_launch(void* const* d_in, const int* in_sizes, int n_in,
                              void* d_out, int out_size)
{
    // Inputs are positional dict order: x, mix, W, b (confirmed by R6: output 0
    // correct with this assignment).
    const float* x   = (const float*)d_in[0];
    const float* mix = (const float*)d_in[1];
    const float* W   = (const float*)d_in[2];
    const float* b   = (const float*)d_in[3];

    float* ybar_out = (float*)d_out;             // elements [0, NCHW)
    float* mix_out  = (float*)d_out + NCHW;      // elements [NCHW, 2*NCHW) = out_size

    // dynamic smem: per-thread acc rows + W slab
    const size_t smem_bytes = (size_t)(BLOCK * ACC_STRIDE + 191 * TT) * sizeof(float);
    cudaFuncSetAttribute(chan_deps_kernel,
                         cudaFuncAttributeMaxDynamicSharedMemorySize,
                         (int)smem_bytes);

    const int grid = NPIX / BLOCK;               // 256, exact
    chan_deps_kernel<<<grid, BLOCK, smem_bytes>>>(x, mix, W, b, ybar_out, mix_out);
}

// round 9
// speedup vs baseline: 1.1403x; 1.1403x over previous
#include <cuda_runtime.h>
#include <cuda_bf16.h>
#include <math.h>

// Shapes: x, mix: [8,192,64,64] fp32 ; W: [191,192] ; b: [191]
// Outputs: ybar then mix_out, each 6291456 floats, contiguous in d_out.
#define CCH   192
#define TT    16            // channel tile
#define NTIL  12            // 192/16
#define BLOCK 128           // threads per block
#define PPT   2             // pixels per thread
#define PIX_PER_BLOCK (BLOCK*PPT)   // 256
#define NPIX  32768         // 8*64*64
#define NCHW  6291456       // 8*192*64*64
#define ACC_STRIDE (2*CCH + 2)      // 386 floats per thread (8B aligned, conflict-free)

__global__ void __launch_bounds__(BLOCK, 1)
chan_deps_kernel(const float* __restrict__ x,
                 const float* __restrict__ mix,
                 const float* __restrict__ W,
                 const float* __restrict__ b,
                 float* __restrict__ ybar_out,
                 float* __restrict__ mix_out)
{
    extern __shared__ float smem[];
    float* acc_s = smem;                          // [BLOCK][ACC_STRIDE] float2-interleaved acc
    float* Wc    = smem + BLOCK * ACC_STRIDE;     // staged W slab, up to 191*16
    float* bs    = Wc + 191 * TT;                 // staged bias, 191

    const int tid = threadIdx.x;
    const int p0  = blockIdx.x * PIX_PER_BLOCK + tid;   // pixel 0
    const int p1  = p0 + BLOCK;                         // pixel 1
    const int base0 = ((p0 >> 12) * CCH << 12) + (p0 & 4095);
    const int base1 = ((p1 >> 12) * CCH << 12) + (p1 & 4095);

    float* accp = acc_s + tid * ACC_STRIDE;

    // zero per-thread accumulators (both pixels interleaved)
    {
        const float2 z = make_float2(0.f, 0.f);
        #pragma unroll 8
        for (int c = 0; c < CCH; c++)
            *reinterpret_cast<float2*>(accp + 2 * c) = z;
    }

    // stage bias once
    for (int i = tid; i < CCH - 1; i += BLOCK) bs[i] = __ldg(&b[i]);

    for (int t = 0; t < NTIL; t++) {
        const int cbase = t * TT;
        const int cend  = cbase + TT;
        const int nrows = (CCH - 1) - cbase;      // W rows cbase .. 190

        // ---- stage W slab: Wc[r][j] = W[cbase+r][cbase+j], j = 0..15 (float4 loads)
        __syncthreads();                           // prior tile done reading Wc
        for (int idx = tid; idx < nrows * 4; idx += BLOCK) {
            const int r = idx >> 2;
            const int q = idx & 3;
            reinterpret_cast<float4*>(Wc)[idx] =
                __ldg(reinterpret_cast<const float4*>(&W[(cbase + r) * CCH + cbase]) + q);
        }
        __syncthreads();

        // ---- load this tile's x / mix for both pixels (coalesced)
        float xv0[TT], mv0[TT], xv1[TT], mv1[TT];
        #pragma unroll
        for (int i = 0; i < TT; i++) {
            const int co = (cbase + i) << 12;
            xv0[i] = __ldg(&x[base0 + co]);
            mv0[i] = __ldg(&mix[base0 + co]);
            xv1[i] = __ldg(&x[base1 + co]);
            mv1[i] = __ldg(&mix[base1 + co]);
        }

        // ---- sequential in-tile recurrence
        float part0[TT], part1[TT];
        #pragma unroll
        for (int i = 0; i < TT; i++) { part0[i] = 0.f; part1[i] = 0.f; }

        float yr0[TT], yr1[TT];
        #pragma unroll
        for (int i = 0; i < TT; i++) {
            const int c = cbase + i;
            float m0, m1;
            if (i == 0 && cbase == 0) {            // channel 0: no conv, no bias
                m0 = mv0[0];
                m1 = mv1[0];
            } else {
                const float2 a = *reinterpret_cast<const float2*>(accp + 2 * c);
                const float bb = bs[c - 1];
                m0 = a.x + bb + mv0[i] + part0[i];
                m1 = a.y + bb + mv1[i] + part1[i];
            }
            const float y0 = rintf(xv0[i] - m0) + m0;   // half-to-even like jnp.round
            const float y1 = rintf(xv1[i] - m1) + m1;
            yr0[i] = y0;
            yr1[i] = y1;
            const int co = c << 12;
            ybar_out[base0 + co] = y0;
            mix_out [base0 + co] = m0;
            ybar_out[base1 + co] = y1;
            mix_out [base1 + co] = m1;
            // in-tile forward contributions: W[(cbase+i2)-1][c] = Wc[i2-1][i]
            #pragma unroll
            for (int i2 = i + 1; i2 < TT; i2++) {
                const float w = Wc[(i2 - 1) * TT + i];
                part0[i2] = fmaf(w, y0, part0[i2]);
                part1[i2] = fmaf(w, y1, part1[i2]);
            }
        }

        // ---- cross-tile rank-16 update, 4 future channels x 2 pixels per group
        for (int c2 = cend; c2 < CCH; c2 += 4) {
            const float* w0 = Wc + (c2 - 1 - cbase) * TT;
            const float* w1 = w0 + TT;
            const float* w2 = w1 + TT;
            const float* w3 = w2 + TT;
            float s0x = 0.f, s0y = 0.f, s1x = 0.f, s1y = 0.f;
            float s2x = 0.f, s2y = 0.f, s3x = 0.f, s3y = 0.f;
            #pragma unroll
            for (int j = 0; j < TT; j++) {
                const float ya = yr0[j];
                const float yb = yr1[j];
                const float wa = w0[j];
                s0x = fmaf(wa, ya, s0x); s0y = fmaf(wa, yb, s0y);
                const float wb = w1[j];
                s1x = fmaf(wb, ya, s1x); s1y = fmaf(wb, yb, s1y);
                const float wc = w2[j];
                s2x = fmaf(wc, ya, s2x); s2y = fmaf(wc, yb, s2y);
                const float wd = w3[j];
                s3x = fmaf(wd, ya, s3x); s3y = fmaf(wd, yb, s3y);
            }
            float2* ap = reinterpret_cast<float2*>(accp + 2 * c2);
            float2 a0 = ap[0]; a0.x += s0x; a0.y += s0y; ap[0] = a0;
            float2 a1 = ap[1]; a1.x += s1x; a1.y += s1y; ap[1] = a1;
            float2 a2 = ap[2]; a2.x += s2x; a2.y += s2y; ap[2] = a2;
            float2 a3 = ap[3]; a3.x += s3x; a3.y += s3y; ap[3] = a3;
        }
    }
}

extern "C" void kernel_launch(void* const* d_in, const int* in_sizes, int n_in,
                              void* d_out, int out_size)
{
    const float* x   = (const float*)d_in[0];
    const float* mix = (const float*)d_in[1];
    const float* W   = (const float*)d_in[2];
    const float* b   = (const float*)d_in[3];

    float* ybar_out = (float*)d_out;
    float* mix_out  = (float*)d_out + NCHW;

    const size_t smem_bytes =
        (size_t)(BLOCK * ACC_STRIDE + 191 * TT + 191) * sizeof(float);
    cudaFuncSetAttribute(chan_deps_kernel,
                         cudaFuncAttributeMaxDynamicSharedMemorySize,
                         (int)smem_bytes);

    const int grid = NPIX / PIX_PER_BLOCK;        // 128, exact; single balanced wave
    chan_deps_kernel<<<grid, BLOCK, smem_bytes>>>(x, mix, W, b, ybar_out, mix_out);
}